// round 1
// baseline (speedup 1.0000x reference)
#include <cuda_runtime.h>
#include <math.h>

// ---------------------------------------------------------------------------
// MultiScaleAdaptiveElasticityLossWithLame
// Inputs:
//   d_in[0]: deformation_field (2,3,160,192,160) float32
//   d_in[1]: image             (2,1,160,192,160) float32
// Output: scalar float32 loss
// ---------------------------------------------------------------------------

#define D0 160
#define H0 192
#define W0 160
#define D1 80
#define H1 96
#define W1 80
#define D2 40
#define H2 48
#define W2 40

#define VOL0 ((long)D0*H0*W0)   // 4,915,200
#define VOL1 ((long)D1*H1*W1)   // 614,400
#define VOL2 ((long)D2*H2*W2)   // 76,800

// Scratch for downsampled fields (device globals: allocation-free)
__device__ float g_def1[2*3*VOL1];
__device__ float g_img1[2*1*VOL1];
__device__ float g_def2[2*3*VOL2];
__device__ float g_img2[2*1*VOL2];
__device__ double g_acc[3];

// ---------------------------------------------------------------------------
__global__ void init_acc_kernel() {
    if (threadIdx.x < 3) g_acc[threadIdx.x] = 0.0;
}

// ---------------------------------------------------------------------------
// Trilinear downsample with align_corners=True semantics.
// coords = f32(j) * f32((in-1)/(out-1)); i0=floor; w=frac; i1=min(i0+1,in-1)
// planes = 2 * C (batch x channel), each plane independent.
__global__ void downsample_kernel(const float* __restrict__ in, float* __restrict__ out,
                                  int planes,
                                  int Di, int Hi, int Wi,
                                  int Do, int Ho, int Wo,
                                  float rD, float rH, float rW)
{
    long total = (long)planes * Do * Ho * Wo;
    long i = (long)blockIdx.x * blockDim.x + threadIdx.x;
    if (i >= total) return;

    int x = (int)(i % Wo); long t = i / Wo;
    int y = (int)(t % Ho); t /= Ho;
    int z = (int)(t % Do); t /= Do;   // t = plane index

    float cz = (float)z * rD;
    float cy = (float)y * rH;
    float cx = (float)x * rW;
    int z0 = min((int)floorf(cz), Di - 1);
    int y0 = min((int)floorf(cy), Hi - 1);
    int x0 = min((int)floorf(cx), Wi - 1);
    float wz = cz - (float)z0;
    float wy = cy - (float)y0;
    float wx = cx - (float)x0;
    int z1 = min(z0 + 1, Di - 1);
    int y1 = min(y0 + 1, Hi - 1);
    int x1 = min(x0 + 1, Wi - 1);

    const float* p = in + t * (long)Di * Hi * Wi;
    long sD = (long)Hi * Wi;

    const float* pz0 = p + (long)z0 * sD;
    const float* pz1 = p + (long)z1 * sD;
    long oy0 = (long)y0 * Wi, oy1 = (long)y1 * Wi;

    float v000 = __ldg(pz0 + oy0 + x0), v001 = __ldg(pz0 + oy0 + x1);
    float v010 = __ldg(pz0 + oy1 + x0), v011 = __ldg(pz0 + oy1 + x1);
    float v100 = __ldg(pz1 + oy0 + x0), v101 = __ldg(pz1 + oy0 + x1);
    float v110 = __ldg(pz1 + oy1 + x0), v111 = __ldg(pz1 + oy1 + x1);

    float a00 = v000 * (1.f - wx) + v001 * wx;
    float a01 = v010 * (1.f - wx) + v011 * wx;
    float a10 = v100 * (1.f - wx) + v101 * wx;
    float a11 = v110 * (1.f - wx) + v111 * wx;
    float b0 = a00 * (1.f - wy) + a01 * wy;
    float b1 = a10 * (1.f - wy) + a11 * wy;
    out[i] = b0 * (1.f - wz) + b1 * wz;
}

// ---------------------------------------------------------------------------
// Gradients of one scalar field at 4 consecutive W positions.
// torch.gradient semantics: central diff interior, one-sided at edges.
__device__ __forceinline__ void field_grads(const float* __restrict__ f,
                                            int d, int h, int w,
                                            int D, int H, int W,
                                            float4& gD, float4& gH, float4& gW_)
{
    long sH = W;
    long sD = (long)H * W;
    const float* base = f + (long)d * sD + (long)h * sH + w;

    float4 c = __ldg(reinterpret_cast<const float4*>(base));

    // W-axis gradient
    float xl = (w > 0)      ? __ldg(base - 1) : 0.f;
    float xr = (w + 4 < W)  ? __ldg(base + 4) : 0.f;
    gW_.x = (w == 0)      ? (c.y - c.x) : 0.5f * (c.y - xl);
    gW_.y = 0.5f * (c.z - c.x);
    gW_.z = 0.5f * (c.w - c.y);
    gW_.w = (w + 4 == W)  ? (c.w - c.z) : 0.5f * (xr - c.z);

    // H-axis gradient: hm/hp clamp to c at the edges, scale switches 0.5 -> 1
    float4 hm = __ldg(reinterpret_cast<const float4*>(base - (h > 0     ? sH : 0)));
    float4 hp = __ldg(reinterpret_cast<const float4*>(base + (h < H - 1 ? sH : 0)));
    float sh = (h == 0 || h == H - 1) ? 1.0f : 0.5f;
    gH.x = sh * (hp.x - hm.x);
    gH.y = sh * (hp.y - hm.y);
    gH.z = sh * (hp.z - hm.z);
    gH.w = sh * (hp.w - hm.w);

    // D-axis gradient
    float4 dm = __ldg(reinterpret_cast<const float4*>(base - (d > 0     ? sD : 0)));
    float4 dp = __ldg(reinterpret_cast<const float4*>(base + (d < D - 1 ? sD : 0)));
    float sd = (d == 0 || d == D - 1) ? 1.0f : 0.5f;
    gD.x = sd * (dp.x - dm.x);
    gD.y = sd * (dp.y - dm.y);
    gD.z = sd * (dp.z - dm.z);
    gD.w = sd * (dp.w - dm.w);
}

__device__ __forceinline__ float energy_lane(float duD, float duH, float duW,
                                             float dvD, float dvH, float dvW,
                                             float dwD, float dwH, float dwW,
                                             float giD, float giH, float giW)
{
    float Exx = duD, Eyy = dvH, Ezz = dwW;
    float Exy = 0.5f * (duH + dvD);
    float Exz = 0.5f * (duW + dwD);
    float Eyz = 0.5f * (dvW + dwH);
    float tr = Exx + Eyy + Ezz;
    float g = sqrtf(giD * giD + giH * giH + giW * giW);
    float lam = 1.0f + 0.5f * g;     // LAMBDA_0 + KAPPA_LAMBDA * g
    float mu  = 1.0f + 0.5f * g;     // MU_0 + KAPPA_MU * g
    float e = 0.5f * lam * tr * tr
            + mu * (Exx * Exx + Eyy * Eyy + Ezz * Ezz
                    + 2.0f * (Exy * Exy + Exz * Exz + Eyz * Eyz));
    return (1.0f + 0.1f * g) * e;    // BASE_WEIGHT + GRADIENT_SCALING * g
}

// ---------------------------------------------------------------------------
// Energy + reduction: one thread handles 4 consecutive W voxels.
__global__ void energy_kernel(const float* __restrict__ def,
                              const float* __restrict__ img,
                              int D, int H, int W, int scale_idx)
{
    const int Wq = W >> 2;
    long total = 2L * D * H * Wq;
    long i = (long)blockIdx.x * blockDim.x + threadIdx.x;

    float local = 0.f;
    if (i < total) {
        int xq = (int)(i % Wq); long t = i / Wq;
        int h = (int)(t % H); t /= H;
        int d = (int)(t % D);
        int n = (int)(t / D);
        int w = xq << 2;

        long vol = (long)D * H * W;
        const float* u  = def + ((long)n * 3 + 0) * vol;
        const float* v  = def + ((long)n * 3 + 1) * vol;
        const float* wf = def + ((long)n * 3 + 2) * vol;
        const float* ic = img + (long)n * vol;

        float4 uD, uH, uW, vD, vH, vW, wD, wH, wW, iD, iH, iW;
        field_grads(u,  d, h, w, D, H, W, uD, uH, uW);
        field_grads(v,  d, h, w, D, H, W, vD, vH, vW);
        field_grads(wf, d, h, w, D, H, W, wD, wH, wW);
        field_grads(ic, d, h, w, D, H, W, iD, iH, iW);

        local  = energy_lane(uD.x, uH.x, uW.x, vD.x, vH.x, vW.x, wD.x, wH.x, wW.x, iD.x, iH.x, iW.x);
        local += energy_lane(uD.y, uH.y, uW.y, vD.y, vH.y, vW.y, wD.y, wH.y, wW.y, iD.y, iH.y, iW.y);
        local += energy_lane(uD.z, uH.z, uW.z, vD.z, vH.z, vW.z, wD.z, wH.z, wW.z, iD.z, iH.z, iW.z);
        local += energy_lane(uD.w, uH.w, uW.w, vD.w, vH.w, vW.w, wD.w, wH.w, wW.w, iD.w, iH.w, iW.w);
    }

    // Block reduction
    #pragma unroll
    for (int o = 16; o > 0; o >>= 1)
        local += __shfl_down_sync(0xffffffffu, local, o);

    __shared__ float ws[8];
    int lane = threadIdx.x & 31;
    int wid  = threadIdx.x >> 5;
    if (lane == 0) ws[wid] = local;
    __syncthreads();
    if (wid == 0) {
        float s = (lane < (blockDim.x >> 5)) ? ws[lane] : 0.f;
        #pragma unroll
        for (int o = 4; o > 0; o >>= 1)
            s += __shfl_down_sync(0xffffffffu, s, o);
        if (lane == 0)
            atomicAdd(&g_acc[scale_idx], (double)s);
    }
}

// ---------------------------------------------------------------------------
__global__ void finalize_kernel(float* out) {
    double m0 = g_acc[0] / (2.0 * VOL0);
    double m1 = g_acc[1] / (2.0 * VOL1);
    double m2 = g_acc[2] / (2.0 * VOL2);
    out[0] = (float)(m0 + m1 + m2);
}

// ---------------------------------------------------------------------------
extern "C" void kernel_launch(void* const* d_in, const int* in_sizes, int n_in,
                              void* d_out, int out_size)
{
    const float* def = (const float*)d_in[0];
    const float* img = (const float*)d_in[1];
    float* out = (float*)d_out;

    float *p_def1, *p_img1, *p_def2, *p_img2;
    cudaGetSymbolAddress((void**)&p_def1, g_def1);
    cudaGetSymbolAddress((void**)&p_img1, g_img1);
    cudaGetSymbolAddress((void**)&p_def2, g_def2);
    cudaGetSymbolAddress((void**)&p_img2, g_img2);

    init_acc_kernel<<<1, 32>>>();

    const int TB = 256;

    // ---- scale 0: full resolution, identity resize ----
    {
        long total = 2L * D0 * H0 * (W0 / 4);
        energy_kernel<<<(int)((total + TB - 1) / TB), TB>>>(def, img, D0, H0, W0, 0);
    }

    // ---- scale 1: downsample then energy ----
    {
        float rD = (float)((double)(D0 - 1) / (double)(D1 - 1));
        float rH = (float)((double)(H0 - 1) / (double)(H1 - 1));
        float rW = (float)((double)(W0 - 1) / (double)(W1 - 1));
        long td = 2L * 3 * VOL1;
        downsample_kernel<<<(int)((td + TB - 1) / TB), TB>>>(def, p_def1, 6,
                                                             D0, H0, W0, D1, H1, W1, rD, rH, rW);
        long ti = 2L * 1 * VOL1;
        downsample_kernel<<<(int)((ti + TB - 1) / TB), TB>>>(img, p_img1, 2,
                                                             D0, H0, W0, D1, H1, W1, rD, rH, rW);
        long total = 2L * D1 * H1 * (W1 / 4);
        energy_kernel<<<(int)((total + TB - 1) / TB), TB>>>(p_def1, p_img1, D1, H1, W1, 1);
    }

    // ---- scale 2: downsample then energy ----
    {
        float rD = (float)((double)(D0 - 1) / (double)(D2 - 1));
        float rH = (float)((double)(H0 - 1) / (double)(H2 - 1));
        float rW = (float)((double)(W0 - 1) / (double)(W2 - 1));
        long td = 2L * 3 * VOL2;
        downsample_kernel<<<(int)((td + TB - 1) / TB), TB>>>(def, p_def2, 6,
                                                             D0, H0, W0, D2, H2, W2, rD, rH, rW);
        long ti = 2L * 1 * VOL2;
        downsample_kernel<<<(int)((ti + TB - 1) / TB), TB>>>(img, p_img2, 2,
                                                             D0, H0, W0, D2, H2, W2, rD, rH, rW);
        long total = 2L * D2 * H2 * (W2 / 4);
        energy_kernel<<<(int)((total + TB - 1) / TB), TB>>>(p_def2, p_img2, D2, H2, W2, 2);
    }

    finalize_kernel<<<1, 1>>>(out);
}